// round 5
// baseline (speedup 1.0000x reference)
#include <cuda_runtime.h>
#include <cuda_bf16.h>
#include <cstdint>

// Sparsemax along last dim of a [ROWS, 32000] fp32 matrix.
//
// Exact, sort-free: tau solves sum_i max(x_i - tau, 0) = 1 and tau >= rowmax-1,
// so the support lies in C = {x > rowmax - 1} (~25 elems/row for Gaussian data).
//
// One CTA per row, 512 threads, 3 CTAs/SM (launch_bounds). Three streaming
// passes over the row:
//   pass 1: LDG from DRAM, block max (warp reduce + shared atomicMax)
//   pass 2: re-read (L2-resident), compact C into SMEM
//   ---     every warp redundantly runs Michelot on C (exact tau, no bcast)
//   pass 3: re-read (L2, last-use) and store max(x - tau, 0) with __stcs
// High occupancy cross-covers the reduce/Michelot latency phases between the
// three resident CTAs, keeping HBM busy without any explicit pipeline.

#define SMX_N       32000
#define SMX_N4      8000
#define SMX_T       512
#define SMX_VPT     16          // 16*512 = 8192 >= 8000 float4
#define SMX_NEG     (-3.0e38f)
#define SMX_CAP     1024

// order-preserving float<->uint for shared atomicMax
__device__ __forceinline__ unsigned smx_enc(float f) {
    unsigned b = __float_as_uint(f);
    return (b & 0x80000000u) ? ~b : (b | 0x80000000u);
}
__device__ __forceinline__ float smx_dec(unsigned u) {
    return (u & 0x80000000u) ? __uint_as_float(u & 0x7fffffffu)
                             : __uint_as_float(~u);
}

__global__ __launch_bounds__(SMX_T, 3)
void sparsemax_kernel(const float* __restrict__ x, float* __restrict__ y) {
    const int t    = threadIdx.x;
    const int lane = t & 31;

    __shared__ unsigned s_maxbits;
    __shared__ int      s_cnt;
    __shared__ float    s_red[2][2];
    __shared__ float    s_cand[SMX_CAP];

    if (t == 0) { s_maxbits = 0u; s_cnt = 0; }
    __syncthreads();

    const float4* __restrict__ xr =
        reinterpret_cast<const float4*>(x + (size_t)blockIdx.x * SMX_N);
    float4* __restrict__ yr =
        reinterpret_cast<float4*>(y + (size_t)blockIdx.x * SMX_N);

    // ---- pass 1: block max ----
    float m = SMX_NEG;
    #pragma unroll
    for (int i = 0; i < SMX_VPT; i++) {
        const int idx = i * SMX_T + t;
        if (idx < SMX_N4) {
            const float4 v = __ldg(&xr[idx]);
            m = fmaxf(m, fmaxf(fmaxf(v.x, v.y), fmaxf(v.z, v.w)));
        }
    }
    #pragma unroll
    for (int o = 16; o; o >>= 1)
        m = fmaxf(m, __shfl_xor_sync(0xffffffffu, m, o));
    if (lane == 0) atomicMax(&s_maxbits, smx_enc(m));
    __syncthreads();
    const float thr = smx_dec(s_maxbits) - 1.0f;   // tau >= thr always

    // ---- pass 2: compact candidates {x > thr} (row is L2-resident) ----
    #pragma unroll
    for (int i = 0; i < SMX_VPT; i++) {
        const int idx = i * SMX_T + t;
        if (idx < SMX_N4) {
            const float4 v = __ldg(&xr[idx]);
            if (v.x > thr) { int k = atomicAdd(&s_cnt, 1); if (k < SMX_CAP) s_cand[k] = v.x; }
            if (v.y > thr) { int k = atomicAdd(&s_cnt, 1); if (k < SMX_CAP) s_cand[k] = v.y; }
            if (v.z > thr) { int k = atomicAdd(&s_cnt, 1); if (k < SMX_CAP) s_cand[k] = v.z; }
            if (v.w > thr) { int k = atomicAdd(&s_cnt, 1); if (k < SMX_CAP) s_cand[k] = v.w; }
        }
    }
    __syncthreads();
    const int cnt = s_cnt;

    float tau;
    if (cnt <= SMX_CAP) {
        // ---- every warp redundantly: Michelot on the candidate list ----
        tau = thr;
        float prevc = -1.0f;
        #pragma unroll 1
        for (int it = 0; it < 64; it++) {
            float s = 0.0f, c = 0.0f;
            for (int j = lane; j < cnt; j += 32) {
                const float z = s_cand[j];
                if (z > tau) { s += z; c += 1.0f; }
            }
            #pragma unroll
            for (int o = 16; o; o >>= 1) {
                s += __shfl_xor_sync(0xffffffffu, s, o);
                c += __shfl_xor_sync(0xffffffffu, c, o);
            }
            tau = (s - 1.0f) / c;
            if (c == prevc) break;          // fixed point: exact tau
            prevc = c;
        }
    } else {
        // ---- fallback (never expected): streaming Michelot over the row ----
        if (t == 0) { s_red[0][0] = 0.f; s_red[0][1] = 0.f;
                      s_red[1][0] = 0.f; s_red[1][1] = 0.f; }
        __syncthreads();
        tau = thr;
        float prevc = -1.0f;
        unsigned q = 0;
        #pragma unroll 1
        for (int it = 0; it < 64; it++) {
            float s = 0.0f, c = 0.0f;
            for (int i = 0; i < SMX_VPT; i++) {
                const int idx = i * SMX_T + t;
                if (idx < SMX_N4) {
                    const float4 v = __ldg(&xr[idx]);
                    if (v.x > tau) { s += v.x; c += 1.0f; }
                    if (v.y > tau) { s += v.y; c += 1.0f; }
                    if (v.z > tau) { s += v.z; c += 1.0f; }
                    if (v.w > tau) { s += v.w; c += 1.0f; }
                }
            }
            #pragma unroll
            for (int o = 16; o; o >>= 1) {
                s += __shfl_xor_sync(0xffffffffu, s, o);
                c += __shfl_xor_sync(0xffffffffu, c, o);
            }
            if (lane == 0) { atomicAdd(&s_red[q][0], s); atomicAdd(&s_red[q][1], c); }
            if (t == 0)    { s_red[q ^ 1][0] = 0.f; s_red[q ^ 1][1] = 0.f; }
            __syncthreads();
            const float S = s_red[q][0], C = s_red[q][1];
            __syncthreads();
            tau = (S - 1.0f) / C;
            if (C == prevc) break;
            prevc = C;
            q ^= 1;
        }
    }

    // ---- pass 3: output max(x - tau, 0); streaming hints ----
    #pragma unroll
    for (int i = 0; i < SMX_VPT; i++) {
        const int idx = i * SMX_T + t;
        if (idx < SMX_N4) {
            float4 v;
            asm("ld.global.lu.v4.f32 {%0,%1,%2,%3}, [%4];"
                : "=f"(v.x), "=f"(v.y), "=f"(v.z), "=f"(v.w)
                : "l"(&xr[idx]));
            float4 o;
            o.x = fmaxf(v.x - tau, 0.0f);
            o.y = fmaxf(v.y - tau, 0.0f);
            o.z = fmaxf(v.z - tau, 0.0f);
            o.w = fmaxf(v.w - tau, 0.0f);
            __stcs(&yr[idx], o);
        }
    }
}

extern "C" void kernel_launch(void* const* d_in, const int* in_sizes, int n_in,
                              void* d_out, int out_size) {
    const float* x = (const float*)d_in[0];
    float* y = (float*)d_out;
    const int rows = in_sizes[0] / SMX_N;
    sparsemax_kernel<<<rows, SMX_T>>>(x, y);
}

// round 6
// speedup vs baseline: 1.7460x; 1.7460x over previous
#include <cuda_runtime.h>
#include <cuda_bf16.h>
#include <cstdint>

// Sparsemax along last dim of a [ROWS, 32000] fp32 matrix.
//
// Exact, sort-free: tau solves sum_i max(x_i - tau, 0) = 1 and tau >= rowmax-1,
// so the support lies in C = {x > rowmax - 1} (~25 elems/row, Gaussian data).
//
// Persistent CTAs (grid = #SMs, 1024 threads). Whole row TMA'd into a single
// 128 KB SMEM buffer one row ahead; row is register-resident (8 x float4 per
// thread). Per row only TWO block barriers:
//   barrier A: after LDS copy + shared atomicMax  -> releases buffer for the
//              next row's TMA (t0 issues it) and publishes rowmax
//   barrier B: after candidate compaction (shared atomicAdd)
// All 32 warps then redundantly run Michelot on the tiny candidate list
// (no broadcast barrier), and the output is stored with evict-first hints.

#define SMX_N        32000
#define SMX_N4       8000
#define SMX_ROWBYTES 128000
#define SMX_THREADS  1024
#define SMX_VPT      8
#define SMX_NEG      (-3.0e38f)
#define SMX_CAP      1024

__device__ __forceinline__ uint32_t smx_smem_u32(const void* p) {
    uint32_t a;
    asm("{ .reg .u64 t; cvta.to.shared.u64 t, %1; cvt.u32.u64 %0, t; }"
        : "=r"(a) : "l"(p));
    return a;
}
__device__ __forceinline__ void smx_mbar_init(uint32_t mbar, uint32_t count) {
    asm volatile("mbarrier.init.shared.b64 [%0], %1;" :: "r"(mbar), "r"(count) : "memory");
}
__device__ __forceinline__ void smx_expect_tx(uint32_t mbar, uint32_t bytes) {
    asm volatile("mbarrier.arrive.expect_tx.shared.b64 _, [%0], %1;"
                 :: "r"(mbar), "r"(bytes) : "memory");
}
__device__ __forceinline__ void smx_bulk_g2s(uint32_t dst, const void* src,
                                             uint32_t bytes, uint32_t mbar) {
    asm volatile(
        "cp.async.bulk.shared::cta.global.mbarrier::complete_tx::bytes [%0], [%1], %2, [%3];"
        :: "r"(dst), "l"(src), "r"(bytes), "r"(mbar) : "memory");
}
__device__ __forceinline__ void smx_mbar_wait(uint32_t mbar, uint32_t parity) {
    asm volatile(
        "{\n\t"
        ".reg .pred P;\n\t"
        "SMXW%=:\n\t"
        "mbarrier.try_wait.parity.acquire.cta.shared::cta.b64 P, [%0], %1, 0x989680;\n\t"
        "@P bra SMXD%=;\n\t"
        "bra SMXW%=;\n\t"
        "SMXD%=:\n\t"
        "}"
        :: "r"(mbar), "r"(parity) : "memory");
}
__device__ __forceinline__ void smx_fence_async() {
    asm volatile("fence.proxy.async.shared::cta;" ::: "memory");
}

// order-preserving float<->uint for shared atomicMax
__device__ __forceinline__ unsigned smx_enc(float f) {
    unsigned b = __float_as_uint(f);
    return (b & 0x80000000u) ? ~b : (b | 0x80000000u);
}
__device__ __forceinline__ float smx_dec(unsigned u) {
    return (u & 0x80000000u) ? __uint_as_float(u & 0x7fffffffu)
                             : __uint_as_float(~u);
}

extern __shared__ float smx_buf[];   // 32000 floats = 128 KB

__global__ __launch_bounds__(SMX_THREADS, 1)
void sparsemax_kernel(const float* __restrict__ x, float* __restrict__ y, int rows) {
    const int t    = threadIdx.x;
    const int lane = t & 31;
    const int stride = gridDim.x;

    __shared__ __align__(8) uint64_t s_mbar;
    __shared__ unsigned s_maxbits[2];
    __shared__ int      s_cnt[2];
    __shared__ float    s_red[2][2];          // fallback accumulators
    __shared__ float    s_cand[2][SMX_CAP];

    const uint32_t mbar = smx_smem_u32(&s_mbar);
    const uint32_t sbuf = smx_smem_u32(smx_buf);

    if (t == 0) {
        smx_mbar_init(mbar, 1);
        s_maxbits[0] = 0u;  s_cnt[0] = 0;
        s_maxbits[1] = 0u;  s_cnt[1] = 0;
    }
    __syncthreads();

    const int row0 = blockIdx.x;
    if (row0 >= rows) return;

    if (t == 0) {
        smx_expect_tx(mbar, SMX_ROWBYTES);
        smx_bulk_g2s(sbuf, x + (size_t)row0 * SMX_N, SMX_ROWBYTES, mbar);
    }

    uint32_t parity = 0;   // mbarrier phase
    unsigned p = 0;        // row-parity for scratch slots

    for (int r = row0; r < rows; r += stride) {
        smx_mbar_wait(mbar, parity);
        parity ^= 1u;

        // ---- SMEM -> registers with fused running max ----
        float4 v[SMX_VPT];
        float m = SMX_NEG;
        const float4* s4 = reinterpret_cast<const float4*>(smx_buf);
        #pragma unroll
        for (int i = 0; i < SMX_VPT; i++) {
            const int idx = i * SMX_THREADS + t;
            if (idx < SMX_N4) {
                v[i] = s4[idx];
                m = fmaxf(m, fmaxf(fmaxf(v[i].x, v[i].y), fmaxf(v[i].z, v[i].w)));
            } else {
                v[i] = make_float4(SMX_NEG, SMX_NEG, SMX_NEG, SMX_NEG);
            }
        }

        // warp max-reduce + shared atomicMax (pre-barrier)
        #pragma unroll
        for (int o = 16; o; o >>= 1)
            m = fmaxf(m, __shfl_xor_sync(0xffffffffu, m, o));
        if (lane == 0) atomicMax(&s_maxbits[p], smx_enc(m));

        __syncthreads();   // barrier A: buffer reads done + rowmax published

        // t0: release buffer to the async proxy, prefetch next row
        if (t == 0 && r + stride < rows) {
            smx_fence_async();
            smx_expect_tx(mbar, SMX_ROWBYTES);
            smx_bulk_g2s(sbuf, x + (size_t)(r + stride) * SMX_N, SMX_ROWBYTES, mbar);
        }

        const float thr = smx_dec(s_maxbits[p]) - 1.0f;   // tau >= thr always
        if (t == 1) { s_maxbits[p ^ 1] = 0u; s_cnt[p ^ 1] = 0; }  // prep next slot

        // ---- compact candidates {x > thr} into s_cand[p] ----
        #pragma unroll
        for (int i = 0; i < SMX_VPT; i++) {
            const float a0 = v[i].x, a1 = v[i].y, a2 = v[i].z, a3 = v[i].w;
            if (a0 > thr) { int k = atomicAdd(&s_cnt[p], 1); if (k < SMX_CAP) s_cand[p][k] = a0; }
            if (a1 > thr) { int k = atomicAdd(&s_cnt[p], 1); if (k < SMX_CAP) s_cand[p][k] = a1; }
            if (a2 > thr) { int k = atomicAdd(&s_cnt[p], 1); if (k < SMX_CAP) s_cand[p][k] = a2; }
            if (a3 > thr) { int k = atomicAdd(&s_cnt[p], 1); if (k < SMX_CAP) s_cand[p][k] = a3; }
        }
        __syncthreads();   // barrier B: candidate list complete
        const int cnt = s_cnt[p];

        float tau;
        if (cnt <= SMX_CAP) {
            // ---- every warp redundantly: Michelot on the candidate list ----
            tau = thr;
            float prevc = -1.0f;
            #pragma unroll 1
            for (int it = 0; it < 64; it++) {
                float s = 0.0f, c = 0.0f;
                for (int j = lane; j < cnt; j += 32) {
                    const float z = s_cand[p][j];
                    if (z > tau) { s += z; c += 1.0f; }
                }
                #pragma unroll
                for (int o = 16; o; o >>= 1) {
                    s += __shfl_xor_sync(0xffffffffu, s, o);
                    c += __shfl_xor_sync(0xffffffffu, c, o);
                }
                tau = (s - 1.0f) / c;
                if (c == prevc) break;        // fixed point: exact tau
                prevc = c;
            }
        } else {
            // ---- fallback: full-row Michelot via shared atomics (rare) ----
            if (t == 0) { s_red[0][0] = 0.f; s_red[0][1] = 0.f;
                          s_red[1][0] = 0.f; s_red[1][1] = 0.f; }
            __syncthreads();
            tau = thr;
            float prevc = -1.0f;
            unsigned q = 0;
            #pragma unroll 1
            for (int it = 0; it < 64; it++) {
                float s = 0.0f, c = 0.0f;
                #pragma unroll
                for (int i = 0; i < SMX_VPT; i++) {
                    if (v[i].x > tau) { s += v[i].x; c += 1.0f; }
                    if (v[i].y > tau) { s += v[i].y; c += 1.0f; }
                    if (v[i].z > tau) { s += v[i].z; c += 1.0f; }
                    if (v[i].w > tau) { s += v[i].w; c += 1.0f; }
                }
                #pragma unroll
                for (int o = 16; o; o >>= 1) {
                    s += __shfl_xor_sync(0xffffffffu, s, o);
                    c += __shfl_xor_sync(0xffffffffu, c, o);
                }
                if (lane == 0) { atomicAdd(&s_red[q][0], s); atomicAdd(&s_red[q][1], c); }
                if (t == 0)    { s_red[q ^ 1][0] = 0.f; s_red[q ^ 1][1] = 0.f; }
                __syncthreads();
                const float S = s_red[q][0], C = s_red[q][1];
                __syncthreads();
                tau = (S - 1.0f) / C;
                if (C == prevc) break;
                prevc = C;
                q ^= 1;
            }
        }

        // ---- output: max(x - tau, 0), coalesced, evict-first ----
        float4* __restrict__ yr = reinterpret_cast<float4*>(y + (size_t)r * SMX_N);
        #pragma unroll
        for (int i = 0; i < SMX_VPT; i++) {
            const int idx = i * SMX_THREADS + t;
            if (idx < SMX_N4) {
                float4 o;
                o.x = fmaxf(v[i].x - tau, 0.0f);
                o.y = fmaxf(v[i].y - tau, 0.0f);
                o.z = fmaxf(v[i].z - tau, 0.0f);
                o.w = fmaxf(v[i].w - tau, 0.0f);
                __stcs(&yr[idx], o);
            }
        }

        p ^= 1u;
    }
}

extern "C" void kernel_launch(void* const* d_in, const int* in_sizes, int n_in,
                              void* d_out, int out_size) {
    const float* x = (const float*)d_in[0];
    float* y = (float*)d_out;
    const int rows = in_sizes[0] / SMX_N;

    int dev = 0, sms = 148;
    cudaGetDevice(&dev);
    cudaDeviceGetAttribute(&sms, cudaDevAttrMultiProcessorCount, dev);

    static bool attr_done = false;
    if (!attr_done) {
        cudaFuncSetAttribute(sparsemax_kernel,
                             cudaFuncAttributeMaxDynamicSharedMemorySize,
                             SMX_ROWBYTES);
        attr_done = true;
    }

    int grid = rows < sms ? rows : sms;
    sparsemax_kernel<<<grid, SMX_THREADS, SMX_ROWBYTES>>>(x, y, rows);
}